// round 1
// baseline (speedup 1.0000x reference)
#include <cuda_runtime.h>

#define NB   64      // batch
#define NT   1024    // timesteps
#define NIN  256     // input dim
#define NH   512     // hidden dim
#define NCTA 128     // persistent CTAs (<= 148 SMs -> co-resident, barrier safe)
#define NTHR 256

// ---------------- device globals (scratch; no allocations allowed) ----------
__device__ unsigned g_bar;                 // monotonic grid-barrier counter
__device__ float    g_fr[2][NB * NH];      // double-buffered firing rates

__global__ void init_kernel() { g_bar = 0u; }

// ---------------- Phase A: v_in = x @ W_in + b_in  -> written into d_out ----
// A: [NB*NT, NIN] row-major, B: [NIN, NH] row-major, C: [NB*NT, NH]
#define BM 64
#define BN 64
#define BK 16

__global__ __launch_bounds__(256) void gemm_vin(const float* __restrict__ A,
                                                const float* __restrict__ Bm,
                                                const float* __restrict__ bias,
                                                float* __restrict__ C) {
    __shared__ float As[BK][BM + 4];   // [kk][m], padded
    __shared__ float Bs[BK][BN];       // [kk][n]
    const int tid = threadIdx.x;
    const int m0 = blockIdx.y * BM;
    const int n0 = blockIdx.x * BN;
    const int tx = tid & 15;    // n group (4 cols each)
    const int ty = tid >> 4;    // m group (4 rows each)

    float acc[4][4];
#pragma unroll
    for (int i = 0; i < 4; ++i)
#pragma unroll
        for (int j = 0; j < 4; ++j) acc[i][j] = 0.f;

    for (int k0 = 0; k0 < NIN; k0 += BK) {
        // load A tile 64x16 (k fastest for coalescing), store transposed
#pragma unroll
        for (int i = tid; i < BM * BK; i += 256) {
            int m = i >> 4, kk = i & 15;
            As[kk][m] = A[(long)(m0 + m) * NIN + k0 + kk];
        }
        // load B tile 16x64
#pragma unroll
        for (int i = tid; i < BK * BN; i += 256) {
            int kk = i >> 6, nn = i & 63;
            Bs[kk][nn] = Bm[(long)(k0 + kk) * NH + n0 + nn];
        }
        __syncthreads();

#pragma unroll
        for (int kk = 0; kk < BK; ++kk) {
            float a[4], b[4];
#pragma unroll
            for (int i = 0; i < 4; ++i) a[i] = As[kk][ty * 4 + i];
#pragma unroll
            for (int j = 0; j < 4; ++j) b[j] = Bs[kk][tx * 4 + j];
#pragma unroll
            for (int i = 0; i < 4; ++i)
#pragma unroll
                for (int j = 0; j < 4; ++j)
                    acc[i][j] = fmaf(a[i], b[j], acc[i][j]);
        }
        __syncthreads();
    }

#pragma unroll
    for (int i = 0; i < 4; ++i) {
        const int m = m0 + ty * 4 + i;
#pragma unroll
        for (int j = 0; j < 4; ++j) {
            const int n = n0 + tx * 4 + j;
            C[(long)m * NH + n] = acc[i][j] + bias[n];
        }
    }
}

// ---------------- Phase B: persistent recurrent kernel ----------------------
// 128 CTAs = 4 batch-blocks (16 batches) x 32 col-blocks (16 hidden cols).
// W_hid slice [512 x 16] lives in SMEM (c-major, padded stride 516 for
// conflict-free float4 reads). v state lives in one register per thread.
// fr exchanged through L2 (__stcg/__ldcg) with a monotonic grid barrier.

#define WSTRIDE 516   // 512 + 4 floats: (c*129 + k4) % 8 covers all bank quads

__global__ __launch_bounds__(NTHR, 1) void step_kernel(
    const float* __restrict__ W_hid,
    const float* __restrict__ b_hid,
    const float* __restrict__ alpha,
    const float* __restrict__ init_state,
    float* __restrict__ out) {
    extern __shared__ float sh[];
    float* Wsm = sh;                    // [16][WSTRIDE]  (c-major)
    float* frs = sh + 16 * WSTRIDE;     // [16][512]      (b-major)

    const int tid = threadIdx.x;
    const int bb  = blockIdx.x >> 5;    // 0..3
    const int cb  = blockIdx.x & 31;    // 0..31
    const int B0  = bb * 16;
    const int C0  = cb * 16;
    const int c   = tid & 15;
    const int b   = tid >> 4;           // 0..15
    const int gb  = B0 + b;
    const int gc  = C0 + c;

    // one-time W slice load: Wsm[cc][k] = W_hid[k][C0+cc]
    for (int i = tid; i < 16 * NH; i += NTHR) {
        int k = i >> 4, cc = i & 15;
        Wsm[cc * WSTRIDE + k] = W_hid[(long)k * NH + C0 + cc];
    }

    // init state
    float v  = init_state[gb * NH + gc];
    float fr = fmaxf(v, 0.f);
    __stcg(&g_fr[0][gb * NH + gc], fr);
    const float a   = alpha[gc];
    const float bh  = b_hid[gc];
    const float oma = 1.f - a;

    unsigned epoch = 0;
    auto gbar = [&](unsigned target) {
        __syncthreads();
        if (tid == 0) {
            __threadfence();                 // release: fr writes visible in L2
            atomicAdd(&g_bar, 1u);
            while (*((volatile unsigned*)&g_bar) < target) { }
            __threadfence();                 // acquire-ish
        }
        __syncthreads();
    };

    ++epoch;
    gbar(epoch * NCTA);   // fr[0] + Wsm ready everywhere

    int p = 0;
    for (int t = 0; t < NT; ++t) {
        // stage fr(t-1) for my 16 batches into SMEM (L2-coherent loads)
        const float4* src = (const float4*)(&g_fr[p][B0 * NH]);
        float4* dst = (float4*)frs;
        for (int i = tid; i < (16 * NH) / 4; i += NTHR)
            dst[i] = __ldcg(src + i);
        __syncthreads();

        // dot product: vhid(b,c) = sum_k fr[b][k] * W_hid[k][c]
        float a0 = 0.f, a1 = 0.f, a2 = 0.f, a3 = 0.f;
        const float4* f4 = (const float4*)(frs + b * NH);
        const float4* w4 = (const float4*)(Wsm + c * WSTRIDE);
#pragma unroll 8
        for (int k4 = 0; k4 < NH / 4; ++k4) {
            float4 f = f4[k4];
            float4 w = w4[k4];
            a0 = fmaf(f.x, w.x, a0);
            a1 = fmaf(f.y, w.y, a1);
            a2 = fmaf(f.z, w.z, a2);
            a3 = fmaf(f.w, w.w, a3);
        }
        const float vhid = (a0 + a1) + (a2 + a3) + bh;

        // leaky-integrator update; v_in was pre-stored in out[], overwrite w/ fr
        const long oidx = ((long)gb * NT + t) * NH + gc;
        const float vin = out[oidx];
        v  = oma * v + a * (vhid + vin);
        fr = fmaxf(v, 0.f);
        out[oidx] = fr;
        __stcg(&g_fr[p ^ 1][gb * NH + gc], fr);

        ++epoch;
        gbar(epoch * NCTA);   // also covers SMEM frs reuse next iter
        p ^= 1;
    }
}

// ---------------- launch ----------------------------------------------------
extern "C" void kernel_launch(void* const* d_in, const int* in_sizes, int n_in,
                              void* d_out, int out_size) {
    const float* x     = (const float*)d_in[0];
    const float* init  = (const float*)d_in[1];
    const float* W_in  = (const float*)d_in[2];
    const float* b_in  = (const float*)d_in[3];
    const float* W_hid = (const float*)d_in[4];
    const float* b_hid = (const float*)d_in[5];
    const float* alpha = (const float*)d_in[6];
    float* out = (float*)d_out;

    const int smem = (16 * WSTRIDE + 16 * NH) * (int)sizeof(float);  // 65792 B
    cudaFuncSetAttribute(step_kernel, cudaFuncAttributeMaxDynamicSharedMemorySize, smem);

    init_kernel<<<1, 1>>>();

    dim3 grid(NH / BN, (NB * NT) / BM);   // (8, 1024)
    gemm_vin<<<grid, 256>>>(x, W_in, b_in, out);

    step_kernel<<<NCTA, NTHR, smem>>>(W_hid, b_hid, alpha, init, out);
}

// round 2
// speedup vs baseline: 1.4112x; 1.4112x over previous
#include <cuda_runtime.h>

#define NB   64      // batch
#define NT   1024    // timesteps
#define NIN  256     // input dim
#define NH   512     // hidden dim
#define NCTA 128     // persistent CTAs (<=148 SMs -> co-resident)
#define NTHR 256

#define FSTR 20      // padded row stride (floats) for Wsm/frs: conflict-free quads
#define RST  336     // reduce-buffer row stride (floats): 16*20 + 16 pad

// ---------------- device globals (scratch; no allocations allowed) ----------
__device__ unsigned g_bar;                    // monotonic grid-barrier counter
__device__ float    g_fr[2][NH * NB];         // TRANSPOSED: [hid][batch]

__global__ void init_kernel() { g_bar = 0u; }

// ---------------- Phase A: v_in = x @ W_in + b_in  -> written into d_out ----
#define BM 64
#define BN 64
#define BK 16

__global__ __launch_bounds__(256) void gemm_vin(const float* __restrict__ A,
                                                const float* __restrict__ Bm,
                                                const float* __restrict__ bias,
                                                float* __restrict__ C) {
    __shared__ float As[BK][BM + 4];
    __shared__ float Bs[BK][BN];
    const int tid = threadIdx.x;
    const int m0 = blockIdx.y * BM;
    const int n0 = blockIdx.x * BN;
    const int tx = tid & 15;
    const int ty = tid >> 4;

    float acc[4][4];
#pragma unroll
    for (int i = 0; i < 4; ++i)
#pragma unroll
        for (int j = 0; j < 4; ++j) acc[i][j] = 0.f;

    for (int k0 = 0; k0 < NIN; k0 += BK) {
#pragma unroll
        for (int i = tid; i < BM * BK; i += 256) {
            int m = i >> 4, kk = i & 15;
            As[kk][m] = A[(long)(m0 + m) * NIN + k0 + kk];
        }
#pragma unroll
        for (int i = tid; i < BK * BN; i += 256) {
            int kk = i >> 6, nn = i & 63;
            Bs[kk][nn] = Bm[(long)(k0 + kk) * NH + n0 + nn];
        }
        __syncthreads();

#pragma unroll
        for (int kk = 0; kk < BK; ++kk) {
            float a[4], b[4];
#pragma unroll
            for (int i = 0; i < 4; ++i) a[i] = As[kk][ty * 4 + i];
#pragma unroll
            for (int j = 0; j < 4; ++j) b[j] = Bs[kk][tx * 4 + j];
#pragma unroll
            for (int i = 0; i < 4; ++i)
#pragma unroll
                for (int j = 0; j < 4; ++j)
                    acc[i][j] = fmaf(a[i], b[j], acc[i][j]);
        }
        __syncthreads();
    }

#pragma unroll
    for (int i = 0; i < 4; ++i) {
        const int m = m0 + ty * 4 + i;
#pragma unroll
        for (int j = 0; j < 4; ++j) {
            const int n = n0 + tx * 4 + j;
            C[(long)m * NH + n] = acc[i][j] + bias[n];
        }
    }
}

// ---------------- Phase B: persistent recurrent kernel ----------------------
// 128 CTAs = 4 batch-blocks (16 batches) x 32 col-blocks (16 hidden cols).
// Register tiling: thread (kt, bg, cg) computes 4b x 4c partials over a
// K-slice; kt pairs reduced via shfl, remaining 8 via SMEM.
// Layouts (k-major, FSTR=20 pad): Wsm[k][16c], frs[k][16b] -> conflict-free
// LDS.128 with 4x broadcast. g_fr kept transposed [hid][batch] so staging is
// a straight vector copy (no on-the-fly transpose).

#define ROWFMA(accv, s, w)                          \
    accv.x = fmaf(s, w.x, accv.x);                  \
    accv.y = fmaf(s, w.y, accv.y);                  \
    accv.z = fmaf(s, w.z, accv.z);                  \
    accv.w = fmaf(s, w.w, accv.w);

__global__ __launch_bounds__(NTHR, 1) void step_kernel(
    const float* __restrict__ W_hid,
    const float* __restrict__ b_hid,
    const float* __restrict__ alpha,
    const float* __restrict__ init_state,
    float* __restrict__ out) {
    extern __shared__ float sh[];
    float* Wsm = sh;                       // [NH][FSTR]  (k-major, c in row)
    float* frs = sh + NH * FSTR;           // [NH][FSTR]  (k-major, b in row)
    float* red = sh + 2 * NH * FSTR;       // [8][RST]

    const int tid = threadIdx.x;
    const int bb  = blockIdx.x >> 5;       // 0..3
    const int cb  = blockIdx.x & 31;       // 0..31
    const int B0  = bb * 16;
    const int C0  = cb * 16;

    // compute-role ids
    const int kt = tid >> 4;               // 0..15 (K slice)
    const int bg = (tid >> 2) & 3;         // batch group
    const int cg = tid & 3;                // col group
    // epilogue-role ids (tid -> output (b,c))
    const int eb = tid >> 4;
    const int ec = tid & 15;
    const int gb = B0 + eb;
    const int gc = C0 + ec;

    // one-time W slice load: Wsm[k][c] = W_hid[k][C0+c]
    for (int i = tid; i < NH * 16; i += NTHR) {
        int k = i >> 4, c = i & 15;
        Wsm[k * FSTR + c] = W_hid[(long)k * NH + C0 + c];
    }

    // init state (g_fr transposed: [hid][batch])
    float v  = init_state[gb * NH + gc];
    float fr = fmaxf(v, 0.f);
    __stcg(&g_fr[0][gc * NB + gb], fr);
    const float al  = alpha[gc];
    const float bh  = b_hid[gc];
    const float oma = 1.f - al;

    unsigned epoch = 0;
    auto gbar = [&](unsigned target) {
        __syncthreads();
        if (tid == 0) {
            __threadfence();
            atomicAdd(&g_bar, 1u);
            while (*((volatile unsigned*)&g_bar) < target) { }
            __threadfence();
        }
        __syncthreads();
    };

    ++epoch;
    gbar(epoch * NCTA);   // Wsm + g_fr[0] visible everywhere

    const float* fbase = frs + kt * 4 * FSTR + bg * 4;
    const float* wbase = Wsm + kt * 4 * FSTR + cg * 4;

    int p = 0;
    for (int t = 0; t < NT; ++t) {
        const long oidx = ((long)gb * NT + t) * NH + gc;
        const float vin = out[oidx];   // prefetch v_in (overlaps with staging+FMA)

        // stage fr(t-1): frs[k][0..15] = g_fr[p][k][B0..B0+15]  (straight copy)
        {
            const float* src = &g_fr[p][0];
            for (int i = tid; i < NH * 4; i += NTHR) {     // 2048 float4
                int k = i >> 2, q = i & 3;
                float4 v4 = __ldcg((const float4*)(src + k * NB + B0) + q);
                *(float4*)(frs + k * FSTR + q * 4) = v4;
            }
        }
        __syncthreads();

        // register-tiled partial GEMM over K slice: k4 = iter*16 + kt
        float4 acc0 = {0,0,0,0}, acc1 = {0,0,0,0}, acc2 = {0,0,0,0}, acc3 = {0,0,0,0};
#pragma unroll
        for (int it = 0; it < 8; ++it) {
            const float* fp = fbase + it * 64 * FSTR;
            const float* wp = wbase + it * 64 * FSTR;
#pragma unroll
            for (int kk = 0; kk < 4; ++kk) {
                float4 f = *(const float4*)(fp + kk * FSTR);
                float4 w = *(const float4*)(wp + kk * FSTR);
                ROWFMA(acc0, f.x, w);
                ROWFMA(acc1, f.y, w);
                ROWFMA(acc2, f.z, w);
                ROWFMA(acc3, f.w, w);
            }
        }

        // intra-warp reduce over kt-pair (tid ^ 16 shares warp, same (bg,cg))
#pragma unroll
        for (int m = 0; m < 1; ++m) {
            acc0.x += __shfl_xor_sync(0xffffffffu, acc0.x, 16);
            acc0.y += __shfl_xor_sync(0xffffffffu, acc0.y, 16);
            acc0.z += __shfl_xor_sync(0xffffffffu, acc0.z, 16);
            acc0.w += __shfl_xor_sync(0xffffffffu, acc0.w, 16);
            acc1.x += __shfl_xor_sync(0xffffffffu, acc1.x, 16);
            acc1.y += __shfl_xor_sync(0xffffffffu, acc1.y, 16);
            acc1.z += __shfl_xor_sync(0xffffffffu, acc1.z, 16);
            acc1.w += __shfl_xor_sync(0xffffffffu, acc1.w, 16);
            acc2.x += __shfl_xor_sync(0xffffffffu, acc2.x, 16);
            acc2.y += __shfl_xor_sync(0xffffffffu, acc2.y, 16);
            acc2.z += __shfl_xor_sync(0xffffffffu, acc2.z, 16);
            acc2.w += __shfl_xor_sync(0xffffffffu, acc2.w, 16);
            acc3.x += __shfl_xor_sync(0xffffffffu, acc3.x, 16);
            acc3.y += __shfl_xor_sync(0xffffffffu, acc3.y, 16);
            acc3.z += __shfl_xor_sync(0xffffffffu, acc3.z, 16);
            acc3.w += __shfl_xor_sync(0xffffffffu, acc3.w, 16);
        }

        // kt-even threads publish 8 partial rows
        if ((kt & 1) == 0) {
            float* rp = red + (kt >> 1) * RST + (bg * 4) * FSTR + cg * 4;
            *(float4*)(rp + 0 * FSTR) = acc0;
            *(float4*)(rp + 1 * FSTR) = acc1;
            *(float4*)(rp + 2 * FSTR) = acc2;
            *(float4*)(rp + 3 * FSTR) = acc3;
        }
        __syncthreads();

        // final reduce + leaky-integrator update (thread owns output (eb,ec))
        float s = 0.f;
#pragma unroll
        for (int r = 0; r < 8; ++r)
            s += red[r * RST + eb * FSTR + ec];

        const float vhid = s + bh;
        v  = oma * v + al * (vhid + vin);
        fr = fmaxf(v, 0.f);
        out[oidx] = fr;
        __stcg(&g_fr[p ^ 1][gc * NB + gb], fr);

        ++epoch;
        gbar(epoch * NCTA);
        p ^= 1;
    }
}

// ---------------- launch ----------------------------------------------------
extern "C" void kernel_launch(void* const* d_in, const int* in_sizes, int n_in,
                              void* d_out, int out_size) {
    const float* x     = (const float*)d_in[0];
    const float* init  = (const float*)d_in[1];
    const float* W_in  = (const float*)d_in[2];
    const float* b_in  = (const float*)d_in[3];
    const float* W_hid = (const float*)d_in[4];
    const float* b_hid = (const float*)d_in[5];
    const float* alpha = (const float*)d_in[6];
    float* out = (float*)d_out;

    const int smem = (2 * NH * FSTR + 8 * RST) * (int)sizeof(float);  // ~92.7 KB
    cudaFuncSetAttribute(step_kernel, cudaFuncAttributeMaxDynamicSharedMemorySize, smem);

    init_kernel<<<1, 1>>>();

    dim3 grid(NH / BN, (NB * NT) / BM);   // (8, 1024)
    gemm_vin<<<grid, 256>>>(x, W_in, b_in, out);

    step_kernel<<<NCTA, NTHR, smem>>>(W_hid, b_hid, alpha, init, out);
}